// round 3
// baseline (speedup 1.0000x reference)
#include <cuda_runtime.h>
#include <math.h>

#define SIZE 512
#define NB 16
#define L 1534
#define NC 16
#define O1 1023
#define O2 512
#define BN_EPS 1e-3f

// ---------------- scratch (no allocations allowed) ----------------
__device__ float g_partial[4 * NB * 1024];   // [kb][b][o]  (o padded to 1024)
__device__ float g_h1[NB * 1024];            // [b][o]      (o padded to 1024)
__device__ float g_h2[NB * O2];              // [b][o2]

// packed fp32x2 FMA (sm_103a FFMA2 path)
__device__ __forceinline__ void ffma2(unsigned long long &acc,
                                      unsigned long long a,
                                      unsigned long long w) {
    asm("fma.rn.f32x2 %0, %1, %2, %0;" : "+l"(acc) : "l"(a), "l"(w));
}

// =====================================================================
// Kernel A: stage-1 partial sums.
// grid (64 o-tiles, 4 s-chunks), block 128 threads.
//   g  = t & 15      : s-split within chunk (16-way)
//   q  = (t>>4) & 3  : o-quad  (4 o per thread -> 16 o per block)
//   bh = t >> 6      : batch half (8 b per thread)
// Each thread iterates absolute rows r = obase + sbase + d (d = g + 16i),
// sharing each x row across its 4 outputs (s_loc = d - oo).
// =====================================================================
__global__ __launch_bounds__(128) void k_stage1(const float* __restrict__ x,
                                                const float* __restrict__ W1) {
    const int t  = threadIdx.x;
    const int g  = t & 15;
    const int q  = (t >> 4) & 3;
    const int bh = t >> 6;
    const int o0    = blockIdx.x * 16;
    const int kb    = blockIdx.y;
    const int obase = o0 + q * 4;
    const int sbase = kb * 128;

    unsigned long long acc[4][8];
    #pragma unroll
    for (int oo = 0; oo < 4; oo++)
        #pragma unroll
        for (int b = 0; b < 8; b++) acc[oo][b] = 0ull;

    #pragma unroll
    for (int i = 0; i < 9; i++) {
        const int d = g + (i << 4);
        if (d > 130) break;            // max useful d = 127 + 3
        const int r = obase + sbase + d;
        const bool xok = (r < L);

        const float* wp[4];
        bool wok[4];
        #pragma unroll
        for (int oo = 0; oo < 4; oo++) {
            int sl = d - oo;
            int og = obase + oo;
            wok[oo] = (sl >= 0) && (sl < 128) && (og < O1);
            int slc = sl < 0 ? 0 : (sl > 127 ? 127 : sl);
            int ogc = og < O1 ? og : (O1 - 1);
            wp[oo] = W1 + (ogc * (SIZE * NC) + (sbase + slc) * NC);
        }
        const float* xp = x + ((bh * 8) * L + r) * NC;

        #pragma unroll
        for (int h = 0; h < 4; h++) {          // 4 channels (2 f32x2) per step
            ulonglong2 w[4];
            #pragma unroll
            for (int oo = 0; oo < 4; oo++) {
                ulonglong2 wv; wv.x = 0ull; wv.y = 0ull;
                if (wok[oo])
                    wv = *reinterpret_cast<const ulonglong2*>(wp[oo] + h * 4);
                w[oo] = wv;
            }
            #pragma unroll
            for (int b = 0; b < 8; b++) {
                ulonglong2 xv; xv.x = 0ull; xv.y = 0ull;
                if (xok)
                    xv = *reinterpret_cast<const ulonglong2*>(xp + b * (L * NC) + h * 4);
                #pragma unroll
                for (int oo = 0; oo < 4; oo++) {
                    ffma2(acc[oo][b], xv.x, w[oo].x);
                    ffma2(acc[oo][b], xv.y, w[oo].y);
                }
            }
        }
    }

    // cross-thread (g) reduction: smem [g][o_local*16 + b], padded 256->257
    __shared__ float2 red[16 * 257];
    #pragma unroll
    for (int oo = 0; oo < 4; oo++)
        #pragma unroll
        for (int b = 0; b < 8; b++)
            red[g * 257 + (q * 4 + oo) * 16 + bh * 8 + b] =
                *reinterpret_cast<float2*>(&acc[oo][b]);
    __syncthreads();

    #pragma unroll
    for (int pp = 0; pp < 2; pp++) {
        const int p  = t + pp * 128;       // (o_local, b) pair
        const int ol = p >> 4;
        const int b  = p & 15;
        float sx = 0.f, sy = 0.f;
        #pragma unroll
        for (int gg = 0; gg < 16; gg++) {
            float2 v = red[gg * 257 + p];
            sx += v.x; sy += v.y;
        }
        const int og = o0 + ol;
        if (og < O1)
            g_partial[(kb * NB + b) * 1024 + og] = sx + sy;
    }
}

// =====================================================================
// Kernel A2: combine 4 s-chunk partials + bias + ELU -> h1
// grid 64, block 256 (16*1024 outputs)
// =====================================================================
__global__ __launch_bounds__(256) void k_h1(const float* __restrict__ b1) {
    const int idx = blockIdx.x * 256 + threadIdx.x;
    const int b = idx >> 10;
    const int o = idx & 1023;
    float v = 0.f;
    if (o < O1) {
        float s = g_partial[(0 * NB + b) * 1024 + o]
                + g_partial[(1 * NB + b) * 1024 + o]
                + g_partial[(2 * NB + b) * 1024 + o]
                + g_partial[(3 * NB + b) * 1024 + o]
                + b1[o];
        v = (s > 0.f) ? s : expm1f(s);   // ELU(alpha=1)
    }
    g_h1[b * 1024 + o] = v;
}

// =====================================================================
// Kernel B: stage-2  h2[b,o2] = sum_s h1[b,o2+s] * W2[o2,s] + b2[o2]
// grid 128 (4 o2 per block), block 256 (64-way s split)
// =====================================================================
__global__ __launch_bounds__(256) void k_stage2(const float* __restrict__ W2,
                                                const float* __restrict__ b2) {
    const int t   = threadIdx.x;
    const int ol  = t >> 6;
    const int l64 = t & 63;
    const int o2  = blockIdx.x * 4 + ol;

    float acc[NB];
    #pragma unroll
    for (int b = 0; b < NB; b++) acc[b] = 0.f;

    #pragma unroll
    for (int i = 0; i < 8; i++) {
        const int s = l64 + (i << 6);
        const float w = W2[o2 * SIZE + s];
        #pragma unroll
        for (int b = 0; b < NB; b++)
            acc[b] = fmaf(g_h1[b * 1024 + o2 + s], w, acc[b]);
    }

    __shared__ float red[4 * 64 * 17];
    #pragma unroll
    for (int b = 0; b < NB; b++)
        red[ol * 1088 + l64 * 17 + b] = acc[b];
    __syncthreads();

    if (t < 64) {
        const int olr = t >> 4;
        const int b   = t & 15;
        float s = 0.f;
        #pragma unroll
        for (int j = 0; j < 64; j++)
            s += red[olr * 1088 + j * 17 + b];
        const int o2g = blockIdx.x * 4 + olr;
        g_h2[b * O2 + o2g] = s + b2[o2g];
    }
}

// =====================================================================
// Kernel C+D: gate g[b] = (h2.Wl + bl) * sigmoid(h2.Ws + bs), then
// out[b,l,c] = ((xpad[b,l,c] + g[b]) - mean[c]) * rsqrt(var[c]+eps)*gamma[c] + beta[c]
// grid (16 b, 8 row-chunks), block 256. Gate recomputed per block (tiny).
// =====================================================================
__global__ __launch_bounds__(256) void k_out(const float* __restrict__ x,
                                             const float* __restrict__ Wl,
                                             const float* __restrict__ bl,
                                             const float* __restrict__ Ws,
                                             const float* __restrict__ bs,
                                             const float* __restrict__ gamma,
                                             const float* __restrict__ beta,
                                             const float* __restrict__ mean,
                                             const float* __restrict__ var,
                                             float* __restrict__ out) {
    const int b  = blockIdx.x;
    const int cb = blockIdx.y;
    const int t  = threadIdx.x;

    // gate reduction (512-elem dots, 2 elems/thread)
    float h2a = g_h2[b * O2 + t];
    float h2b = g_h2[b * O2 + 256 + t];
    float aL = h2a * Wl[t] + h2b * Wl[256 + t];
    float aS = h2a * Ws[t] + h2b * Ws[256 + t];
    #pragma unroll
    for (int off = 16; off; off >>= 1) {
        aL += __shfl_down_sync(0xffffffffu, aL, off);
        aS += __shfl_down_sync(0xffffffffu, aS, off);
    }
    __shared__ float rL[8], rS[8];
    __shared__ float sa[16], sd[16];
    __shared__ float gsh;
    if ((t & 31) == 0) { rL[t >> 5] = aL; rS[t >> 5] = aS; }
    __syncthreads();
    if (t == 0) {
        float sL = 0.f, sS = 0.f;
        #pragma unroll
        for (int j = 0; j < 8; j++) { sL += rL[j]; sS += rS[j]; }
        sL += bl[0]; sS += bs[0];
        gsh = sL * (1.f / (1.f + expf(-sS)));
    }
    __syncthreads();
    if (t < 16) {
        float sc = gamma[t] * rsqrtf(var[t] + BN_EPS);
        sa[t] = sc;
        sd[t] = beta[t] - mean[t] * sc + gsh * sc;   // folds gate + BN shift
    }
    __syncthreads();

    const int row0 = cb * 192;
    const int rows = min(192, 1535 - row0);
    const float4* x4 = reinterpret_cast<const float4*>(x);
    float4* o4 = reinterpret_cast<float4*>(out);
    for (int j = t; j < rows * 4; j += 256) {
        const int l  = row0 + (j >> 2);
        const int c4 = j & 3;
        float4 xv; xv.x = 0.f; xv.y = 0.f; xv.z = 0.f; xv.w = 0.f;
        if (l < L) xv = x4[(b * L + l) * 4 + c4];
        float4 r;
        const int c = c4 * 4;
        r.x = xv.x * sa[c + 0] + sd[c + 0];
        r.y = xv.y * sa[c + 1] + sd[c + 1];
        r.z = xv.z * sa[c + 2] + sd[c + 2];
        r.w = xv.w * sa[c + 3] + sd[c + 3];
        o4[(b * 1535 + l) * 4 + c4] = r;
    }
}

// =====================================================================
extern "C" void kernel_launch(void* const* d_in, const int* in_sizes, int n_in,
                              void* d_out, int out_size) {
    const float* x     = (const float*)d_in[0];
    const float* W1    = (const float*)d_in[1];
    const float* b1    = (const float*)d_in[2];
    const float* W2    = (const float*)d_in[3];
    const float* b2    = (const float*)d_in[4];
    const float* Wl    = (const float*)d_in[5];
    const float* bl    = (const float*)d_in[6];
    const float* Ws    = (const float*)d_in[7];
    const float* bs    = (const float*)d_in[8];
    const float* gamma = (const float*)d_in[9];
    const float* beta  = (const float*)d_in[10];
    const float* mean  = (const float*)d_in[11];
    const float* var   = (const float*)d_in[12];
    float* out = (float*)d_out;

    k_stage1<<<dim3(64, 4), 128>>>(x, W1);
    k_h1<<<64, 256>>>(b1);
    k_stage2<<<128, 256>>>(W2, b2);
    k_out<<<dim3(16, 8), 256>>>(x, Wl, bl, Ws, bs, gamma, beta, mean, var, out);
}